// round 16
// baseline (speedup 1.0000x reference)
#include <cuda_runtime.h>
#include <cuda_bf16.h>
#include <math.h>

#define Bb 2
#define Nn 286
#define HH 150
#define TE 4            // edges per tile (one tile per WARP)
#define MAXE 82944      // >= B*N*(N+1)/2 = 82082
#define PART 420        // blocks per conv layer
#define CH 38           // k-chunks of 4 (150 -> 152 padded)

// repacked sizes
#define WH_SZ (CH*3*256)    // 29184 floats per hidden matrix
#define WO0_SZ (CH*128)     // 4864
#define WO1_SZ (CH*256)     // 9728

typedef unsigned long long ULL;

// ---------------- device scratch (device-code references ONLY) -------------
__device__ int   g_edge_count;
__device__ int   g_done;
__device__ int   g_packed[MAXE];  // (b<<20)|(i<<10)|j
__device__ float g_dist[MAXE];
__device__ float g_f0[Bb*Nn*4];
__device__ float g_f1[Bb*Nn*8];
__device__ float g_f2[Bb*Nn*8];
__device__ float g_f3[Bb*Nn*8];
__device__ float g_K0[MAXE*32];
__device__ float g_K1[MAXE*64];
__device__ float g_K2[MAXE*64];
// unit-pair repacked weights (see prep_kernel for layout)
__device__ float g_Wh[6][WH_SZ];
__device__ float g_Wo0[WO0_SZ];
__device__ float g_Wo1[WO1_SZ];
__device__ float g_Wo2[WO1_SZ];

__device__ __forceinline__ float sp_act(float x) {
    float t = 5.0f * x;
    if (t > 15.0f) return x;
    return 0.2f * __logf(1.0f + __expf(t));
}

__device__ __forceinline__ void ffma2(ULL &d, ULL a, ULL b) {
    asm("fma.rn.f32x2 %0, %1, %2, %0;" : "+l"(d) : "l"(a), "l"(b));
}
__device__ __forceinline__ float2 unpk(ULL a) {
    float lo, hi; asm("mov.b64 {%0, %1}, %2;" : "=f"(lo), "=f"(hi) : "l"(a));
    return make_float2(lo, hi);
}

// ---------------- reset: counters only (stream-ordered before prep) --------
__global__ void reset_kernel() {
    if (threadIdx.x == 0) { g_edge_count = 0; g_done = 0; }
}

// ---------------- unified prep: zero + embed + build + repack --------------
// blocks [0,18): zero accumulators + embed
// blocks [18,658): edge list build
// blocks [658,1437): weight repack (unit-pair interleaved)
__global__ void prep_kernel(const int* __restrict__ Z, const float* __restrict__ emb,
                            const float* __restrict__ xyz,
                            const float* __restrict__ c0w2, const float* __restrict__ c0w3,
                            const float* __restrict__ c1w2, const float* __restrict__ c1w3,
                            const float* __restrict__ c2w2, const float* __restrict__ c2w3,
                            const float* __restrict__ c0wo, const float* __restrict__ c1wo,
                            const float* __restrict__ c2wo) {
    const int b = blockIdx.x;
    if (b < 18) {
        int t = b*256 + threadIdx.x;
        if (t < Bb*Nn*8) { g_f1[t] = 0.f; g_f2[t] = 0.f; g_f3[t] = 0.f; }
        if (t < Bb*Nn*4) {
            int n = t >> 2, c = t & 3;
            g_f0[t] = emb[Z[n]*4 + c];
        }
        return;
    }
    if (b < 658) {
        int t = (b - 18)*256 + threadIdx.x;
        if (t >= Bb*Nn*Nn) return;
        int bb = t / (Nn*Nn);
        int r = t % (Nn*Nn);
        int i = r / Nn, j = r % Nn;
        if (j < i) return;
        const float* pi = xyz + (bb*Nn + i)*3;
        const float* pj = xyz + (bb*Nn + j)*3;
        float dx = pi[0]-pj[0], dy = pi[1]-pj[1], dz = pi[2]-pj[2];
        float d = sqrtf(dx*dx + dy*dy + dz*dz + 1e-12f);
        if (d <= 3.0f) {
            int idx = atomicAdd(&g_edge_count, 1);
            g_packed[idx] = (bb << 20) | (i << 10) | j;
            g_dist[idx]   = d;
        }
        return;
    }
    // ---- repack ----
    // hidden layout: float4 @ g = (c*3+p)*64 + h2*32 + lane ; elems r: which=r&1, kk=r>>1
    //   k = c*4 + h2*2 + kk ; u = p*64 + which*32 + lane
    int t = (b - 658)*256 + threadIdx.x;
    if (t < 6*WH_SZ) {
        int m = t / WH_SZ, e = t % WH_SZ;
        int g = e >> 2, r = e & 3;
        int which = r & 1, kk = r >> 1;
        int lane = g & 31, h2 = (g >> 5) & 1, cp = g >> 6;
        int p = cp % 3, c = cp / 3;
        int k = c*4 + h2*2 + kk;
        int u = p*64 + which*32 + lane;
        const float* W = (m == 0) ? c0w2 : (m == 1) ? c0w3 :
                         (m == 2) ? c1w2 : (m == 3) ? c1w3 :
                         (m == 4) ? c2w2 : c2w3;
        g_Wh[m][e] = (k < HH && u < HH) ? W[k*HH + u] : 0.f;
        return;
    }
    t -= 6*WH_SZ;
    if (t < WO0_SZ) {   // out0: pairs {o=l, o=l+16}, 16 lanes
        int g = t >> 2, r = t & 3;
        int which = r & 1, kk = r >> 1;
        int l = g & 15, h2 = (g >> 4) & 1, c = g >> 5;
        int k = c*4 + h2*2 + kk;
        int o = which*16 + l;
        g_Wo0[t] = (k < HH) ? c0wo[k*32 + o] : 0.f;
        return;
    }
    t -= WO0_SZ;
    if (t < WO1_SZ) {   // out1: pairs {o=lane, o=lane+32}
        int g = t >> 2, r = t & 3;
        int which = r & 1, kk = r >> 1;
        int lane = g & 31, h2 = (g >> 5) & 1, c = g >> 6;
        int k = c*4 + h2*2 + kk;
        int o = which*32 + lane;
        g_Wo1[t] = (k < HH) ? c1wo[k*64 + o] : 0.f;
        return;
    }
    t -= WO1_SZ;
    if (t < WO1_SZ) {
        int g = t >> 2, r = t & 3;
        int which = r & 1, kk = r >> 1;
        int lane = g & 31, h2 = (g >> 5) & 1, c = g >> 6;
        int k = c*4 + h2*2 + kk;
        int o = which*32 + lane;
        g_Wo2[t] = (k < HH) ? c2wo[k*64 + o] : 0.f;
    }
}

// ---- hidden 150x150: pure packed FFMA2, no broadcast MOVs -----------------
// src rows: 8 floats = {h0,h0,h1,h1,h2,h2,h3,h3} (duplicated activations)
// weights: pair {uA=p*64+lane, uB=uA+32}; acc[p][e] = {sum_uA[e], sum_uB[e]}
__device__ __forceinline__ void hidden4(const float* __restrict__ src,
                                        float* __restrict__ dst,
                                        const float* __restrict__ Wp, int lane) {
    ULL acc[3][4];
    #pragma unroll
    for (int p = 0; p < 3; p++)
        #pragma unroll
        for (int e = 0; e < 4; e++) acc[p][e] = 0ULL;
    #pragma unroll 1
    for (int c = 0; c < CH; c++) {
        ulonglong2 wA[3], wB[3];
        #pragma unroll
        for (int p = 0; p < 3; p++) {
            const float* base = Wp + ((c*3 + p)*64 + lane)*4;
            wA[p] = *reinterpret_cast<const ulonglong2*>(base);        // k0,k1 pairs
            wB[p] = *reinterpret_cast<const ulonglong2*>(base + 128);  // k2,k3 pairs
        }
        #pragma unroll
        for (int ck = 0; ck < 4; ck++) {
            const ulonglong2* hr = reinterpret_cast<const ulonglong2*>(src + (c*4 + ck)*8);
            ulonglong2 h01 = hr[0], h23 = hr[1];
            #pragma unroll
            for (int p = 0; p < 3; p++) {
                ULL w = (ck==0) ? wA[p].x : (ck==1) ? wA[p].y
                      : (ck==2) ? wB[p].x : wB[p].y;
                ffma2(acc[p][0], h01.x, w);
                ffma2(acc[p][1], h01.y, w);
                ffma2(acc[p][2], h23.x, w);
                ffma2(acc[p][3], h23.y, w);
            }
        }
    }
    const float S = 0.0816496580927726f;   // 1/sqrt(150)
    #pragma unroll
    for (int p = 0; p < 3; p++) {
        int uA = p*64 + lane, uB = uA + 32;
        float2 v0 = unpk(acc[p][0]), v1 = unpk(acc[p][1]);
        float2 v2 = unpk(acc[p][2]), v3 = unpk(acc[p][3]);
        if (uA < HH) {
            float a0 = sp_act(v0.x*S), a1 = sp_act(v1.x*S);
            float a2 = sp_act(v2.x*S), a3 = sp_act(v3.x*S);
            float4* dr = reinterpret_cast<float4*>(dst + uA*8);
            dr[0] = make_float4(a0, a0, a1, a1);
            dr[1] = make_float4(a2, a2, a3, a3);
        }
        if (uB < HH) {
            float a0 = sp_act(v0.y*S), a1 = sp_act(v1.y*S);
            float a2 = sp_act(v2.y*S), a3 = sp_act(v3.y*S);
            float4* dr = reinterpret_cast<float4*>(dst + uB*8);
            dr[0] = make_float4(a0, a0, a1, a1);
            dr[1] = make_float4(a2, a2, a3, a3);
        }
    }
}

// ---- output layer DIO=64: pair {o=lane, o=lane+32}, 4 edges ---------------
__device__ __forceinline__ void out64(const float* __restrict__ src,
                                      const float* __restrict__ Wop,
                                      float* __restrict__ Kout, int lane) {
    ULL acc[4];
    #pragma unroll
    for (int e = 0; e < 4; e++) acc[e] = 0ULL;
    #pragma unroll 1
    for (int c = 0; c < CH; c++) {
        const float* base = Wop + (c*64 + lane)*4;
        ulonglong2 wA = *reinterpret_cast<const ulonglong2*>(base);
        ulonglong2 wB = *reinterpret_cast<const ulonglong2*>(base + 128);
        #pragma unroll
        for (int ck = 0; ck < 4; ck++) {
            const ulonglong2* hr = reinterpret_cast<const ulonglong2*>(src + (c*4 + ck)*8);
            ulonglong2 h01 = hr[0], h23 = hr[1];
            ULL w = (ck==0) ? wA.x : (ck==1) ? wA.y : (ck==2) ? wB.x : wB.y;
            ffma2(acc[0], h01.x, w);
            ffma2(acc[1], h01.y, w);
            ffma2(acc[2], h23.x, w);
            ffma2(acc[3], h23.y, w);
        }
    }
    #pragma unroll
    for (int e = 0; e < 4; e++) {
        float2 v = unpk(acc[e]);
        Kout[e*64 + lane]      = v.x;
        Kout[e*64 + 32 + lane] = v.y;
    }
}

// ---- output layer DIO=32: 16 pairs {o=l, o=l+16}, lanes split over edges --
__device__ __forceinline__ void out32(const float* __restrict__ src,
                                      const float* __restrict__ Wop,
                                      float* __restrict__ Kout, int lane) {
    const int pp = lane & 15;
    const int eh = lane >> 4;      // edge half: 0 -> edges 0,1 ; 1 -> edges 2,3
    ULL acc[2];
    acc[0] = 0ULL; acc[1] = 0ULL;
    #pragma unroll 1
    for (int c = 0; c < CH; c++) {
        const float* base = Wop + (c*32 + pp)*4;
        ulonglong2 wA = *reinterpret_cast<const ulonglong2*>(base);
        ulonglong2 wB = *reinterpret_cast<const ulonglong2*>(base + 64);
        #pragma unroll
        for (int ck = 0; ck < 4; ck++) {
            ulonglong2 h = *reinterpret_cast<const ulonglong2*>(src + (c*4 + ck)*8 + eh*4);
            ULL w = (ck==0) ? wA.x : (ck==1) ? wA.y : (ck==2) ? wB.x : wB.y;
            ffma2(acc[0], h.x, w);
            ffma2(acc[1], h.y, w);
        }
    }
    #pragma unroll
    for (int e2 = 0; e2 < 2; e2++) {
        int e = 2*eh + e2;
        float2 v = unpk(acc[e2]);
        Kout[e*32 + pp]      = v.x;
        Kout[e*32 + 16 + pp] = v.y;
    }
}

// ---------------- radial MLP: one 4-edge tile per WARP, barrier-free -------
__global__ __launch_bounds__(128)
void radial_kernel(const float* __restrict__ c0w1, const float* __restrict__ c1w1,
                   const float* __restrict__ c2w1) {
    __shared__ __align__(16) float HA[4][152*8];
    __shared__ __align__(16) float HB[4][152*8];

    const int tid  = threadIdx.x;
    const int wid  = tid >> 5;
    const int lane = tid & 31;
    const int cnt = g_edge_count;
    const int ntiles = (cnt + TE - 1) / TE;
    const int layer = blockIdx.x / PART;
    const int t0 = (blockIdx.x % PART) * 4 + wid;
    const float INV_SQRT3 = 0.5773502691896258f;
    const float PI_2 = 1.5707963267948966f;

    const float* w1 = (layer == 0) ? c0w1 : (layer == 1) ? c1w1 : c2w1;
    const float* Wh2 = g_Wh[layer*2];
    const float* Wh3 = g_Wh[layer*2 + 1];

    float* ha = HA[wid];
    float* hb = HB[wid];

    // zero k-padding rows 150,151 (16 floats each buffer)
    if (lane < 16) { ha[150*8 + lane] = 0.f; hb[150*8 + lane] = 0.f; }

    for (int tile = t0; tile < ntiles; tile += PART*4) {
        // basis: every lane computes all 4 edges (broadcast LDGs)
        float s0[TE], s1[TE], s2[TE];
        #pragma unroll
        for (int e = 0; e < TE; e++) {
            int idx = tile*TE + e;
            float d = (idx < cnt) ? g_dist[idx] : 1e9f;
            float x0 = d * (1.0f/1.5f);
            float x1 = x0 - 1.0f;
            float x2 = x0 - 2.0f;
            float c0 = cosf(PI_2*x0), c1 = cosf(PI_2*x1), c2 = cosf(PI_2*x2);
            s0[e] = (fabsf(x0) < 1.f) ? c0*c0 : 0.f;
            s1[e] = (fabsf(x1) < 1.f) ? c1*c1 : 0.f;
            s2[e] = (fabsf(x2) < 1.f) ? c2*c2 : 0.f;
        }

        // layer 1: basis(3) -> 150, dup-format store
        #pragma unroll
        for (int q = 0; q < 5; q++) {
            int u = q*32 + lane;
            if (u < HH) {
                float wa = w1[u]        * INV_SQRT3;
                float wb = w1[HH + u]   * INV_SQRT3;
                float wc = w1[2*HH + u] * INV_SQRT3;
                float a0 = sp_act(fmaf(s0[0], wa, fmaf(s1[0], wb, s2[0]*wc)));
                float a1 = sp_act(fmaf(s0[1], wa, fmaf(s1[1], wb, s2[1]*wc)));
                float a2 = sp_act(fmaf(s0[2], wa, fmaf(s1[2], wb, s2[2]*wc)));
                float a3 = sp_act(fmaf(s0[3], wa, fmaf(s1[3], wb, s2[3]*wc)));
                float4* dr = reinterpret_cast<float4*>(ha + u*8);
                dr[0] = make_float4(a0, a0, a1, a1);
                dr[1] = make_float4(a2, a2, a3, a3);
            }
        }
        __syncwarp();
        hidden4(ha, hb, Wh2, lane);
        __syncwarp();
        hidden4(hb, ha, Wh3, lane);
        __syncwarp();

        if (layer == 0)      out32(ha, g_Wo0, g_K0 + tile*TE*32, lane);
        else if (layer == 1) out64(ha, g_Wo1, g_K1 + tile*TE*64, lane);
        else                 out64(ha, g_Wo2, g_K2 + tile*TE*64, lane);
        __syncwarp();
    }
}

// ---------------- scatter (layers 0,1) -------------------------------------
template<int LAYER>
__global__ void scatter_kernel() {
    constexpr int DIN  = (LAYER == 0) ? 4 : 8;
    constexpr int DOUT = 8;
    const float* __restrict__ K   = (LAYER == 0) ? g_K0 : g_K1;
    const float* __restrict__ fin = (LAYER == 0) ? g_f0 : g_f1;
    float*       __restrict__ fout= (LAYER == 0) ? g_f1 : g_f2;

    const int cnt = g_edge_count;
    const int total = cnt * DOUT;
    const float scale = rsqrtf(150.0f * (float)DIN);
    for (int t = blockIdx.x*blockDim.x + threadIdx.x; t < total;
         t += gridDim.x*blockDim.x) {
        int e = t / DOUT, a = t % DOUT;
        int p = g_packed[e];
        int b = p >> 20, i = (p >> 10) & 1023, j = p & 1023;
        const float* krow = K + e*(DIN*DOUT) + a*DIN;
        const float* fj = fin + (b*Nn + j)*DIN;
        const float* fi = fin + (b*Nn + i)*DIN;
        float s1 = 0.f, s2 = 0.f;
        #pragma unroll
        for (int ji = 0; ji < DIN; ji++) {
            float w = krow[ji];
            s1 = fmaf(w, fj[ji], s1);
            s2 = fmaf(w, fi[ji], s2);
        }
        atomicAdd(&fout[(b*Nn + i)*DOUT + a], s1 * scale);
        if (i != j) atomicAdd(&fout[(b*Nn + j)*DOUT + a], s2 * scale);
    }
}

// ---------------- scatter layer 2 + fused epilogue (last-block-done) -------
__global__ void scatter2_final_kernel(const float* __restrict__ lin_w,
                                      const float* __restrict__ lin_b,
                                      const float* __restrict__ bn_g,
                                      const float* __restrict__ bn_b,
                                      float* __restrict__ out) {
    constexpr int DIN = 8, DOUT = 8;
    const int cnt = g_edge_count;
    const int total = cnt * DOUT;
    const float scale = rsqrtf(150.0f * 8.0f);
    for (int t = blockIdx.x*blockDim.x + threadIdx.x; t < total;
         t += gridDim.x*blockDim.x) {
        int e = t / DOUT, a = t % DOUT;
        int p = g_packed[e];
        int b = p >> 20, i = (p >> 10) & 1023, j = p & 1023;
        const float* krow = g_K2 + e*(DIN*DOUT) + a*DIN;
        const float* fj = g_f2 + (b*Nn + j)*DIN;
        const float* fi = g_f2 + (b*Nn + i)*DIN;
        float s1 = 0.f, s2 = 0.f;
        #pragma unroll
        for (int ji = 0; ji < DIN; ji++) {
            float w = krow[ji];
            s1 = fmaf(w, fj[ji], s1);
            s2 = fmaf(w, fi[ji], s2);
        }
        atomicAdd(&g_f3[(b*Nn + i)*DOUT + a], s1 * scale);
        if (i != j) atomicAdd(&g_f3[(b*Nn + j)*DOUT + a], s2 * scale);
    }

    __threadfence();
    __shared__ int is_last;
    if (threadIdx.x == 0) {
        int ticket = atomicAdd(&g_done, 1);
        is_last = (ticket == (int)gridDim.x - 1);
    }
    __syncthreads();
    if (!is_last) return;

    __shared__ float pooled[2][24];
    __shared__ float yv[2][24];
    int t = threadIdx.x;
    if (t < 48) {
        int b = t / 24, c = t % 24;
        const float* src; int cc;
        if      (c < 8)  { src = g_f1; cc = c;      }
        else if (c < 16) { src = g_f2; cc = c - 8;  }
        else             { src = g_f3; cc = c - 16; }
        float s = 0.f;
        for (int n = 0; n < Nn; n++) {
            float v = src[(b*Nn + n)*8 + cc];
            s = fmaf(v, v, s);
        }
        pooled[b][c] = sqrtf(s + 1e-12f);
    }
    __syncthreads();
    if (t < 48) {
        int b = t / 24, o = t % 24;
        float s = lin_b[o];
        for (int c = 0; c < 24; c++) s = fmaf(pooled[b][c], lin_w[o*24 + c], s);
        yv[b][o] = s;
    }
    __syncthreads();
    if (t < 24) {
        float y0 = yv[0][t], y1 = yv[1][t];
        float m   = 0.5f * (y0 + y1);
        float d0  = y0 - m, d1 = y1 - m;
        float var = 0.5f * (d0*d0 + d1*d1);
        float inv = 1.0f / sqrtf(var + 1e-5f);
        #pragma unroll
        for (int b = 0; b < 2; b++) {
            float v = (yv[b][t] - m) * inv * bn_g[t] + bn_b[t];
            out[b*24 + t] = (v > 0.f) ? v : 0.2f * v;
        }
    }
}

// ---------------- launch: 6 kernels ----------------------------------------
extern "C" void kernel_launch(void* const* d_in, const int* in_sizes, int n_in,
                              void* d_out, int out_size) {
    const float* xyz   = (const float*)d_in[0];
    const int*   Z     = (const int*)  d_in[1];
    const float* emb   = (const float*)d_in[2];
    const float* c0w1  = (const float*)d_in[3];
    const float* c0w2  = (const float*)d_in[4];
    const float* c0w3  = (const float*)d_in[5];
    const float* c0wo  = (const float*)d_in[6];
    const float* c1w1  = (const float*)d_in[7];
    const float* c1w2  = (const float*)d_in[8];
    const float* c1w3  = (const float*)d_in[9];
    const float* c1wo  = (const float*)d_in[10];
    const float* c2w1  = (const float*)d_in[11];
    const float* c2w2  = (const float*)d_in[12];
    const float* c2w3  = (const float*)d_in[13];
    const float* c2wo  = (const float*)d_in[14];
    const float* lin_w = (const float*)d_in[15];
    const float* lin_b = (const float*)d_in[16];
    const float* bn_g  = (const float*)d_in[17];
    const float* bn_b  = (const float*)d_in[18];
    float* out = (float*)d_out;

    reset_kernel<<<1, 32>>>();
    prep_kernel<<<1437, 256>>>(Z, emb, xyz,
                               c0w2, c0w3, c1w2, c1w3, c2w2, c2w3,
                               c0wo, c1wo, c2wo);
    radial_kernel<<<3*PART, 128>>>(c0w1, c1w1, c2w1);
    scatter_kernel<0><<<296, 256>>>();
    scatter_kernel<1><<<296, 256>>>();
    scatter2_final_kernel<<<296, 256>>>(lin_w, lin_b, bn_g, bn_b, out);
}

// round 17
// speedup vs baseline: 1.5560x; 1.5560x over previous
#include <cuda_runtime.h>
#include <cuda_bf16.h>
#include <math.h>

#define Bb 2
#define Nn 286
#define HH 150
#define TE 4            // edges per tile (one tile per WARP)
#define MAXE 82944      // >= B*N*(N+1)/2 = 82082
#define PART 420        // blocks per conv layer
#define CH 38           // k-chunks of 4 (150 -> 152 padded)
#define UP 160          // padded unit count (5 groups of 32)
#define SCAT_BLOCKS 296 // exactly 2 per SM -> co-resident, spin-sync safe

typedef unsigned long long ULL;

// ---------------- device scratch (device-code references ONLY) -------------
__device__ int   g_edge_count;
__device__ int   g_sync0, g_sync1;
__device__ int   g_packed[MAXE];  // (b<<20)|(i<<10)|j
__device__ float g_dist[MAXE];
__device__ float g_f0[Bb*Nn*4];
__device__ float g_f1[Bb*Nn*8];
__device__ float g_f2[Bb*Nn*8];
__device__ float g_f3[Bb*Nn*8];
__device__ float g_K0[MAXE*32];
__device__ float g_K1[MAXE*64];
__device__ float g_K2[MAXE*64];
// k-interleaved repacked weights: Wh[conv*2+L][c*UP*4 + u*4 + (k%4)]
__device__ float g_Wh[6][CH*UP*4];
__device__ float g_Wo0[CH*32*4];
__device__ float g_Wo1[CH*64*4];
__device__ float g_Wo2[CH*64*4];

__device__ __forceinline__ float sp_act(float x) {
    float t = 5.0f * x;
    if (t > 15.0f) return x;
    return 0.2f * __logf(1.0f + __expf(t));
}

// ---- packed fp32x2 FMA helpers (bit-exact 2x FFMA) ----
__device__ __forceinline__ void ffma2(ULL &d, ULL a, ULL b) {
    asm("fma.rn.f32x2 %0, %1, %2, %0;" : "+l"(d) : "l"(a), "l"(b));
}
__device__ __forceinline__ ULL bcast2(float w) {
    ULL r; asm("mov.b64 %0, {%1, %1};" : "=l"(r) : "f"(w)); return r;
}
__device__ __forceinline__ float2 unpk(ULL a) {
    float lo, hi; asm("mov.b64 {%0, %1}, %2;" : "=f"(lo), "=f"(hi) : "l"(a));
    return make_float2(lo, hi);
}

// ---------------- reset: counters only (stream-ordered before prep) --------
__global__ void reset_kernel() {
    if (threadIdx.x == 0) { g_edge_count = 0; g_sync0 = 0; g_sync1 = 0; }
}

// ---------------- unified prep: zero + embed + build + repack --------------
__global__ void prep_kernel(const int* __restrict__ Z, const float* __restrict__ emb,
                            const float* __restrict__ xyz,
                            const float* __restrict__ c0w2, const float* __restrict__ c0w3,
                            const float* __restrict__ c1w2, const float* __restrict__ c1w3,
                            const float* __restrict__ c2w2, const float* __restrict__ c2w3,
                            const float* __restrict__ c0wo, const float* __restrict__ c1wo,
                            const float* __restrict__ c2wo) {
    const int b = blockIdx.x;
    if (b < 18) {
        int t = b*256 + threadIdx.x;
        if (t < Bb*Nn*8) { g_f1[t] = 0.f; g_f2[t] = 0.f; g_f3[t] = 0.f; }
        if (t < Bb*Nn*4) {
            int n = t >> 2, c = t & 3;
            g_f0[t] = emb[Z[n]*4 + c];
        }
        return;
    }
    if (b < 658) {
        int t = (b - 18)*256 + threadIdx.x;
        if (t >= Bb*Nn*Nn) return;
        int bb = t / (Nn*Nn);
        int r = t % (Nn*Nn);
        int i = r / Nn, j = r % Nn;
        if (j < i) return;
        const float* pi = xyz + (bb*Nn + i)*3;
        const float* pj = xyz + (bb*Nn + j)*3;
        float dx = pi[0]-pj[0], dy = pi[1]-pj[1], dz = pi[2]-pj[2];
        float d = sqrtf(dx*dx + dy*dy + dz*dz + 1e-12f);
        if (d <= 3.0f) {
            int idx = atomicAdd(&g_edge_count, 1);
            g_packed[idx] = (bb << 20) | (i << 10) | j;
            g_dist[idx]   = d;
        }
        return;
    }
    {
        const int HSZ = CH*UP*4;
        const int O32 = CH*32*4, O64 = CH*64*4;
        int t = (b - 658)*256 + threadIdx.x;
        if (t < 6*HSZ) {
            int m = t / HSZ, e = t % HSZ;
            int c = e / (UP*4), r = e % (UP*4), u = r >> 2, ck = r & 3;
            int k = c*4 + ck;
            const float* W = (m == 0) ? c0w2 : (m == 1) ? c0w3 :
                             (m == 2) ? c1w2 : (m == 3) ? c1w3 :
                             (m == 4) ? c2w2 : c2w3;
            g_Wh[m][e] = (u < HH && k < HH) ? W[k*HH + u] : 0.f;
            return;
        }
        t -= 6*HSZ;
        if (t < O32) {
            int c = t / (32*4), r = t % (32*4), u = r >> 2, ck = r & 3;
            int k = c*4 + ck;
            g_Wo0[t] = (k < HH) ? c0wo[k*32 + u] : 0.f;
            return;
        }
        t -= O32;
        if (t < O64) {
            int c = t / (64*4), r = t % (64*4), u = r >> 2, ck = r & 3;
            int k = c*4 + ck;
            g_Wo1[t] = (k < HH) ? c1wo[k*64 + u] : 0.f;
            return;
        }
        t -= O64;
        if (t < O64) {
            int c = t / (64*4), r = t % (64*4), u = r >> 2, ck = r & 3;
            int k = c*4 + ck;
            g_Wo2[t] = (k < HH) ? c2wo[k*64 + u] : 0.f;
        }
    }
}

// ---- store one activated unit row (4 edges) ----
__device__ __forceinline__ void store_row4(float* __restrict__ dst, int row,
                                           const ULL* acc) {
    const float S = 0.0816496580927726f;   // 1/sqrt(150)
    float2 a = unpk(acc[0]), b = unpk(acc[1]);
    float4 o;
    o.x = sp_act(a.x*S); o.y = sp_act(a.y*S);
    o.z = sp_act(b.x*S); o.w = sp_act(b.y*S);
    *reinterpret_cast<float4*>(dst + row*TE) = o;
}

// ---- hidden 150x150, single warp, 5 units/lane, repacked float4 weights ---
__device__ __forceinline__ void hidden4(const float* __restrict__ src,
                                        float* __restrict__ dst,
                                        const float* __restrict__ Wp, int lane) {
    ULL acc[5][2];
    #pragma unroll
    for (int q = 0; q < 5; q++) { acc[q][0] = 0ULL; acc[q][1] = 0ULL; }
    #pragma unroll 1
    for (int c = 0; c < CH; c++) {
        float4 w[5];
        #pragma unroll
        for (int q = 0; q < 5; q++)
            w[q] = *reinterpret_cast<const float4*>(Wp + (c*UP + q*32 + lane)*4);
        #pragma unroll
        for (int ck = 0; ck < 4; ck++) {
            ulonglong2 p = *reinterpret_cast<const ulonglong2*>(src + (c*4 + ck)*TE);
            float wv0 = (ck==0)?w[0].x:(ck==1)?w[0].y:(ck==2)?w[0].z:w[0].w;
            float wv1 = (ck==0)?w[1].x:(ck==1)?w[1].y:(ck==2)?w[1].z:w[1].w;
            float wv2 = (ck==0)?w[2].x:(ck==1)?w[2].y:(ck==2)?w[2].z:w[2].w;
            float wv3 = (ck==0)?w[3].x:(ck==1)?w[3].y:(ck==2)?w[3].z:w[3].w;
            float wv4 = (ck==0)?w[4].x:(ck==1)?w[4].y:(ck==2)?w[4].z:w[4].w;
            ULL d0 = bcast2(wv0), d1 = bcast2(wv1), d2 = bcast2(wv2);
            ULL d3 = bcast2(wv3), d4 = bcast2(wv4);
            ffma2(acc[0][0], p.x, d0); ffma2(acc[0][1], p.y, d0);
            ffma2(acc[1][0], p.x, d1); ffma2(acc[1][1], p.y, d1);
            ffma2(acc[2][0], p.x, d2); ffma2(acc[2][1], p.y, d2);
            ffma2(acc[3][0], p.x, d3); ffma2(acc[3][1], p.y, d3);
            ffma2(acc[4][0], p.x, d4); ffma2(acc[4][1], p.y, d4);
        }
    }
    #pragma unroll
    for (int q = 0; q < 5; q++) {
        int u = q*32 + lane;
        if (u < HH) store_row4(dst, u, acc[q]);
    }
}

// ---- output layer: 150 -> DIO, single warp, repacked weights --------------
template<int DIO>
__device__ __forceinline__ void out4(const float* __restrict__ src,
                                     const float* __restrict__ Wop,
                                     float* __restrict__ Kout, int lane) {
    constexpr int NO = DIO / 32;    // 1 (conv0) or 2
    ULL acc[NO][2];
    #pragma unroll
    for (int n = 0; n < NO; n++) { acc[n][0] = 0ULL; acc[n][1] = 0ULL; }
    #pragma unroll 1
    for (int c = 0; c < CH; c++) {
        float4 w[NO];
        #pragma unroll
        for (int n = 0; n < NO; n++)
            w[n] = *reinterpret_cast<const float4*>(Wop + (c*DIO + n*32 + lane)*4);
        #pragma unroll
        for (int ck = 0; ck < 4; ck++) {
            ulonglong2 p = *reinterpret_cast<const ulonglong2*>(src + (c*4 + ck)*TE);
            #pragma unroll
            for (int n = 0; n < NO; n++) {
                float wv = (ck==0)?w[n].x:(ck==1)?w[n].y:(ck==2)?w[n].z:w[n].w;
                ULL wd = bcast2(wv);
                ffma2(acc[n][0], p.x, wd); ffma2(acc[n][1], p.y, wd);
            }
        }
    }
    #pragma unroll
    for (int n = 0; n < NO; n++) {
        int o = n*32 + lane;
        float2 v0 = unpk(acc[n][0]), v1 = unpk(acc[n][1]);
        Kout[0*DIO + o] = v0.x;
        Kout[1*DIO + o] = v0.y;
        Kout[2*DIO + o] = v1.x;
        Kout[3*DIO + o] = v1.y;
    }
}

// ---------------- radial MLP: one 4-edge tile per WARP, barrier-free -------
__global__ __launch_bounds__(128)
void radial_kernel(const float* __restrict__ c0w1, const float* __restrict__ c1w1,
                   const float* __restrict__ c2w1) {
    __shared__ __align__(16) float HA[4][(HH+2)*TE];
    __shared__ __align__(16) float HB[4][(HH+2)*TE];
    __shared__ float SB[4][12];

    const int tid  = threadIdx.x;
    const int wid  = tid >> 5;
    const int lane = tid & 31;
    const int cnt = g_edge_count;
    const int ntiles = (cnt + TE - 1) / TE;
    const int layer = blockIdx.x / PART;
    const int t0 = (blockIdx.x % PART) * 4 + wid;
    const float INV_SQRT3 = 0.5773502691896258f;
    const float PI_2 = 1.5707963267948966f;

    const float* w1 = (layer == 0) ? c0w1 : (layer == 1) ? c1w1 : c2w1;
    const float* Wh2 = g_Wh[layer*2];
    const float* Wh3 = g_Wh[layer*2 + 1];

    float* ha = HA[wid];
    float* hb = HB[wid];
    float* sb = SB[wid];

    // zero the k-padding rows (150,151)
    if (lane < 2*TE) { ha[HH*TE + lane] = 0.f; hb[HH*TE + lane] = 0.f; }

    for (int tile = t0; tile < ntiles; tile += PART*4) {
        if (lane < TE) {
            int idx = tile*TE + lane;
            float d = (idx < cnt) ? g_dist[idx] : 1e9f;
            float x0 = d * (1.0f/1.5f);
            float x1 = x0 - 1.0f;
            float x2 = x0 - 2.0f;
            float c0 = cosf(PI_2*x0), c1 = cosf(PI_2*x1), c2 = cosf(PI_2*x2);
            sb[lane]     = (fabsf(x0) < 1.f) ? c0*c0 : 0.f;
            sb[4 + lane] = (fabsf(x1) < 1.f) ? c1*c1 : 0.f;
            sb[8 + lane] = (fabsf(x2) < 1.f) ? c2*c2 : 0.f;
        }
        __syncwarp();
        float s0[TE], s1[TE], s2[TE];
        #pragma unroll
        for (int e = 0; e < TE; e++) {
            s0[e] = sb[e]; s1[e] = sb[4 + e]; s2[e] = sb[8 + e];
        }

        // layer 1: basis(3) -> 150
        #pragma unroll
        for (int q = 0; q < 5; q++) {
            int u = q*32 + lane;
            if (u < HH) {
                float wa = w1[u]        * INV_SQRT3;
                float wb = w1[HH + u]   * INV_SQRT3;
                float wc = w1[2*HH + u] * INV_SQRT3;
                float4 o;
                o.x = sp_act(fmaf(s0[0], wa, fmaf(s1[0], wb, s2[0]*wc)));
                o.y = sp_act(fmaf(s0[1], wa, fmaf(s1[1], wb, s2[1]*wc)));
                o.z = sp_act(fmaf(s0[2], wa, fmaf(s1[2], wb, s2[2]*wc)));
                o.w = sp_act(fmaf(s0[3], wa, fmaf(s1[3], wb, s2[3]*wc)));
                *reinterpret_cast<float4*>(ha + u*TE) = o;
            }
        }
        __syncwarp();
        hidden4(ha, hb, Wh2, lane);
        __syncwarp();
        hidden4(hb, ha, Wh3, lane);
        __syncwarp();

        if (layer == 0)      out4<32>(ha, g_Wo0, g_K0 + tile*TE*32, lane);
        else if (layer == 1) out4<64>(ha, g_Wo1, g_K1 + tile*TE*64, lane);
        else                 out4<64>(ha, g_Wo2, g_K2 + tile*TE*64, lane);
        __syncwarp();
    }
}

// ---------------- fused scatter (all 3 layers) + epilogue ------------------
// grid = SCAT_BLOCKS = 2 blocks/SM -> all co-resident, spin-sync is safe.
__device__ __forceinline__ void scatter_phase(const float* __restrict__ K,
                                              const float* __restrict__ fin,
                                              float* __restrict__ fout,
                                              int cnt, int DIN, float scale) {
    const int DOUT = 8;
    const int total = cnt * DOUT;
    for (int t = blockIdx.x*blockDim.x + threadIdx.x; t < total;
         t += gridDim.x*blockDim.x) {
        int e = t / DOUT, a = t % DOUT;
        int p = g_packed[e];
        int b = p >> 20, i = (p >> 10) & 1023, j = p & 1023;
        const float* krow = K + e*(DIN*DOUT) + a*DIN;
        const float* fj = fin + (b*Nn + j)*DIN;
        const float* fi = fin + (b*Nn + i)*DIN;
        float s1 = 0.f, s2 = 0.f;
        for (int ji = 0; ji < DIN; ji++) {
            float w = krow[ji];
            s1 = fmaf(w, fj[ji], s1);
            s2 = fmaf(w, fi[ji], s2);
        }
        atomicAdd(&fout[(b*Nn + i)*DOUT + a], s1 * scale);
        if (i != j) atomicAdd(&fout[(b*Nn + j)*DOUT + a], s2 * scale);
    }
}

__device__ __forceinline__ void grid_sync(int* counter) {
    __syncthreads();
    __threadfence();
    if (threadIdx.x == 0) {
        atomicAdd(counter, 1);
        while (atomicAdd(counter, 0) < SCAT_BLOCKS) { }
    }
    __syncthreads();
    __threadfence();
}

__global__ __launch_bounds__(256)
void scatter_all_kernel(const float* __restrict__ lin_w, const float* __restrict__ lin_b,
                        const float* __restrict__ bn_g,  const float* __restrict__ bn_b,
                        float* __restrict__ out) {
    const int cnt = g_edge_count;
    scatter_phase(g_K0, g_f0, g_f1, cnt, 4, rsqrtf(150.0f * 4.0f));
    grid_sync(&g_sync0);
    scatter_phase(g_K1, g_f1, g_f2, cnt, 8, rsqrtf(150.0f * 8.0f));
    grid_sync(&g_sync1);
    scatter_phase(g_K2, g_f2, g_f3, cnt, 8, rsqrtf(150.0f * 8.0f));

    // epilogue in block 0 after all scatters complete
    __syncthreads();
    __threadfence();
    if (threadIdx.x == 0) atomicAdd(&g_sync0, 1);   // reuse sync0: 296 -> 592
    if (blockIdx.x != 0) return;
    if (threadIdx.x == 0) {
        while (atomicAdd(&g_sync0, 0) < 2*SCAT_BLOCKS) { }
    }
    __syncthreads();
    __threadfence();

    __shared__ float pooled[2][24];
    __shared__ float yv[2][24];
    int t = threadIdx.x;
    if (t < 48) {
        int b = t / 24, c = t % 24;
        const float* src; int cc;
        if      (c < 8)  { src = g_f1; cc = c;      }
        else if (c < 16) { src = g_f2; cc = c - 8;  }
        else             { src = g_f3; cc = c - 16; }
        float s = 0.f;
        for (int n = 0; n < Nn; n++) {
            float v = src[(b*Nn + n)*8 + cc];
            s = fmaf(v, v, s);
        }
        pooled[b][c] = sqrtf(s + 1e-12f);
    }
    __syncthreads();
    if (t < 48) {
        int b = t / 24, o = t % 24;
        float s = lin_b[o];
        for (int c = 0; c < 24; c++) s = fmaf(pooled[b][c], lin_w[o*24 + c], s);
        yv[b][o] = s;
    }
    __syncthreads();
    if (t < 24) {
        float y0 = yv[0][t], y1 = yv[1][t];
        float m   = 0.5f * (y0 + y1);
        float d0  = y0 - m, d1 = y1 - m;
        float var = 0.5f * (d0*d0 + d1*d1);
        float inv = 1.0f / sqrtf(var + 1e-5f);
        #pragma unroll
        for (int b = 0; b < 2; b++) {
            float v = (yv[b][t] - m) * inv * bn_g[t] + bn_b[t];
            out[b*24 + t] = (v > 0.f) ? v : 0.2f * v;
        }
    }
}

// ---------------- launch: 4 kernels ----------------------------------------
extern "C" void kernel_launch(void* const* d_in, const int* in_sizes, int n_in,
                              void* d_out, int out_size) {
    const float* xyz   = (const float*)d_in[0];
    const int*   Z     = (const int*)  d_in[1];
    const float* emb   = (const float*)d_in[2];
    const float* c0w1  = (const float*)d_in[3];
    const float* c0w2  = (const float*)d_in[4];
    const float* c0w3  = (const float*)d_in[5];
    const float* c0wo  = (const float*)d_in[6];
    const float* c1w1  = (const float*)d_in[7];
    const float* c1w2  = (const float*)d_in[8];
    const float* c1w3  = (const float*)d_in[9];
    const float* c1wo  = (const float*)d_in[10];
    const float* c2w1  = (const float*)d_in[11];
    const float* c2w2  = (const float*)d_in[12];
    const float* c2w3  = (const float*)d_in[13];
    const float* c2wo  = (const float*)d_in[14];
    const float* lin_w = (const float*)d_in[15];
    const float* lin_b = (const float*)d_in[16];
    const float* bn_g  = (const float*)d_in[17];
    const float* bn_b  = (const float*)d_in[18];
    float* out = (float*)d_out;

    reset_kernel<<<1, 32>>>();
    prep_kernel<<<1324, 256>>>(Z, emb, xyz,
                               c0w2, c0w3, c1w2, c1w3, c2w2, c2w3,
                               c0wo, c1wo, c2wo);
    radial_kernel<<<3*PART, 128>>>(c0w1, c1w1, c2w1);
    scatter_all_kernel<<<SCAT_BLOCKS, 256>>>(lin_w, lin_b, bn_g, bn_b, out);
}